// round 5
// baseline (speedup 1.0000x reference)
#include <cuda_runtime.h>
#include <math.h>
#include <cstdio>

#define NN 40000
#define EE 640000
#define D  128
#define DOUT 40
#define GR 64
#define SCB 160               // scan blocks (160*256 >= NN)

// ---------------- scratch ----------------------------------------------------
__device__ int   g_degE[NN];
__device__ float g_dis[NN];
__device__ int   g_rowptr[NN + 1];
__device__ int   g_cursor[NN];
__device__ int   g_csrc[EE];
__device__ float g_cnorm[EE];
__device__ float g_h [NN * D];
__device__ float g_y [NN * D];
__device__ float g_h3[NN * DOUT];
__device__ int   g_part[SCB];
__device__ int   g_poff[SCB];
__device__ unsigned long long g_ts[16];
__device__ unsigned int g_reg;

// ---------------- timing stamps ----------------------------------------------
__global__ void k_stamp(int idx) {
    unsigned long long t;
    asm volatile("mov.u64 %0, %%globaltimer;" : "=l"(t));
    g_ts[idx] = t;
}

__global__ void k_print() {
    // one line per kernel_launch call; durations in microseconds
    printf("TSLOG g1=%lld clr=%lld deg=%lld scan=%lld scat=%lld reg=%lld "
           "agg1=%lld g2=%lld agg2=%lld g40=%lld agg40=%lld tot=%lld\n",
           (long long)(g_ts[1] - g_ts[0]) / 1000,
           (long long)(g_ts[2] - g_ts[1]) / 1000,
           (long long)(g_ts[3] - g_ts[2]) / 1000,
           (long long)(g_ts[4] - g_ts[3]) / 1000,
           (long long)(g_ts[5] - g_ts[4]) / 1000,
           (long long)(g_ts[6] - g_ts[5]) / 1000,
           (long long)(g_ts[7] - g_ts[6]) / 1000,
           (long long)(g_ts[8] - g_ts[7]) / 1000,
           (long long)(g_ts[9] - g_ts[8]) / 1000,
           (long long)(g_ts[10] - g_ts[9]) / 1000,
           (long long)(g_ts[11] - g_ts[10]) / 1000,
           (long long)(g_ts[11] - g_ts[0]) / 1000);
}

// ---------------- clear ------------------------------------------------------
__global__ void k_clear() {
    int i = blockIdx.x * blockDim.x + threadIdx.x;
    if (i < NN) g_degE[i] = 0;
    if (i == 0) g_reg = 0u;
}

// ---------------- degree histogram --------------------------------------------
__global__ void k_deg(const int* __restrict__ dst, int E) {
    int e = blockIdx.x * blockDim.x + threadIdx.x;
    if (e < E) atomicAdd(&g_degE[dst[e]], 1);
}

// ---------------- 3-phase scan -------------------------------------------------
__global__ void k_scan_part(int n) {
    __shared__ int sm[256];
    int i = blockIdx.x * 256 + threadIdx.x;
    int v = (i < n) ? g_degE[i] : 0;
    sm[threadIdx.x] = v;
    __syncthreads();
#pragma unroll
    for (int o = 128; o; o >>= 1) {
        if (threadIdx.x < o) sm[threadIdx.x] += sm[threadIdx.x + o];
        __syncthreads();
    }
    if (threadIdx.x == 0) g_part[blockIdx.x] = sm[0];
}

__global__ void k_scan_top() {
    __shared__ int sm[256];
    int t = threadIdx.x;
    sm[t] = (t < SCB) ? g_part[t] : 0;
    __syncthreads();
    for (int o = 1; o < 256; o <<= 1) {
        int v = (t >= o) ? sm[t - o] : 0;
        __syncthreads();
        sm[t] += v;
        __syncthreads();
    }
    if (t < SCB) g_poff[t] = sm[t] - g_part[t];
}

__global__ void k_scan_down(int n, int E) {
    __shared__ int sm[256];
    int t = threadIdx.x;
    int i = blockIdx.x * 256 + t;
    int v = (i < n) ? g_degE[i] : 0;
    sm[t] = v;
    __syncthreads();
    for (int o = 1; o < 256; o <<= 1) {
        int u = (t >= o) ? sm[t - o] : 0;
        __syncthreads();
        sm[t] += u;
        __syncthreads();
    }
    if (i < n) {
        int excl = g_poff[blockIdx.x] + sm[t] - v;
        g_rowptr[i] = excl;
        g_cursor[i] = excl;
        g_dis[i] = rsqrtf((float)(v + 1));
        if (i == n - 1) g_rowptr[n] = E;
    }
}

// ---------------- CSR scatter ---------------------------------------------------
__global__ void k_scatter(const int* __restrict__ src, const int* __restrict__ dst, int E) {
    int e = blockIdx.x * blockDim.x + threadIdx.x;
    if (e >= E) return;
    int s = src[e], d = dst[e];
    int pos = atomicAdd(&g_cursor[d], 1);
    g_csrc[pos]  = s;
    g_cnorm[pos] = g_dis[s] * g_dis[d];
}

// ---------------- reg_loss via CSR: count reverse edges -------------------------
// For edge (s,d): # of edges (d->s) = count of d among sources of edges into s
// = occurrences of d in csrc[rowptr[s] : rowptr[s+1]].
__global__ void k_reg(const int* __restrict__ src, const int* __restrict__ dst, int E) {
    int e = blockIdx.x * blockDim.x + threadIdx.x;
    if (e >= E) return;
    int s = src[e], d = dst[e];
    int p  = g_rowptr[s];
    int pe = g_rowptr[s + 1];
    int c = 0;
    for (; p < pe; p++) c += (g_csrc[p] == d);
    if (c) atomicAdd(&g_reg, (unsigned int)c);
}

// ---------------- SGEMM [M,128]@[128,128] ---------------------------------------
__global__ __launch_bounds__(256) void k_gemm128(const float* __restrict__ X,
                                                 const float* __restrict__ W,
                                                 float* __restrict__ H, int M) {
    extern __shared__ float smf[];
    float* Ws = smf;
    float* Xs = smf + D * D;
    for (int i = threadIdx.x; i < D * D; i += 256) Ws[i] = W[i];

    const int tx = threadIdx.x & 31;
    const int ty = threadIdx.x >> 5;

    for (int t0 = blockIdx.x * GR; t0 < M; t0 += gridDim.x * GR) {
        __syncthreads();
        const float4* Xg = (const float4*)(X + (size_t)t0 * D);
        float4* Xs4 = (float4*)Xs;
        for (int i = threadIdx.x; i < GR * (D / 4); i += 256) Xs4[i] = Xg[i];
        __syncthreads();

        float4 acc[8];
#pragma unroll
        for (int r = 0; r < 8; r++) acc[r] = make_float4(0.f, 0.f, 0.f, 0.f);

        const float* xrow = Xs + ty * 8 * D;
#pragma unroll 4
        for (int k = 0; k < D; k++) {
            float4 wv = *(const float4*)&Ws[k * D + tx * 4];
#pragma unroll
            for (int r = 0; r < 8; r++) {
                float xv = xrow[r * D + k];
                acc[r].x += xv * wv.x;
                acc[r].y += xv * wv.y;
                acc[r].z += xv * wv.z;
                acc[r].w += xv * wv.w;
            }
        }
        float4* Hg = (float4*)(H + (size_t)t0 * D);
#pragma unroll
        for (int r = 0; r < 8; r++)
            Hg[(ty * 8 + r) * (D / 4) + tx] = acc[r];
    }
}

// ---------------- SGEMM [M,128]@[128,40] ----------------------------------------
__global__ __launch_bounds__(256) void k_gemm40(const float* __restrict__ X,
                                                const float* __restrict__ W,
                                                float* __restrict__ H3, int M) {
    __shared__ float Ws[D * DOUT];
    __shared__ float Xs[GR * D];
    for (int i = threadIdx.x; i < D * DOUT; i += 256) Ws[i] = W[i];

    const int tx = threadIdx.x & 7;
    const int ty = threadIdx.x >> 3;

    for (int t0 = blockIdx.x * GR; t0 < M; t0 += gridDim.x * GR) {
        __syncthreads();
        const float4* Xg = (const float4*)(X + (size_t)t0 * D);
        float4* Xs4 = (float4*)Xs;
        for (int i = threadIdx.x; i < GR * (D / 4); i += 256) Xs4[i] = Xg[i];
        __syncthreads();

        float a0[5] = {0, 0, 0, 0, 0};
        float a1[5] = {0, 0, 0, 0, 0};
        const float* x0 = Xs + (ty * 2) * D;
#pragma unroll 4
        for (int k = 0; k < D; k++) {
            float w[5];
#pragma unroll
            for (int j = 0; j < 5; j++) w[j] = Ws[k * DOUT + tx * 5 + j];
            float xa = x0[k];
            float xb = x0[D + k];
#pragma unroll
            for (int j = 0; j < 5; j++) {
                a0[j] += xa * w[j];
                a1[j] += xb * w[j];
            }
        }
        float* o0 = H3 + (size_t)(t0 + ty * 2) * DOUT + tx * 5;
#pragma unroll
        for (int j = 0; j < 5; j++) o0[j] = a0[j];
#pragma unroll
        for (int j = 0; j < 5; j++) o0[DOUT + j] = a1[j];
    }
}

// ---------------- aggregation (128-d): SMEM edge staging ------------------------
__global__ __launch_bounds__(256) void k_agg128(const float* __restrict__ Hh,
                                                const float* __restrict__ b,
                                                float* __restrict__ Y, int n) {
    __shared__ int   ss[8][32];
    __shared__ float sw[8][32];
    const int lane = threadIdx.x & 31;
    const int wrp  = threadIdx.x >> 5;
    const int i = blockIdx.x * 8 + wrp;
    if (i >= n) return;

    const float4* __restrict__ H4 = (const float4*)Hh;
    float d2 = g_dis[i]; d2 *= d2;
    float4 acc = H4[(size_t)i * 32 + lane];
    acc.x *= d2; acc.y *= d2; acc.z *= d2; acc.w *= d2;

    int p = g_rowptr[i];
    const int pe = g_rowptr[i + 1];
    while (p < pe) {
        int cnt = pe - p;
        if (cnt > 32) cnt = 32;
        if (lane < cnt) {
            ss[wrp][lane] = g_csrc[p + lane];
            sw[wrp][lane] = g_cnorm[p + lane];
        }
        __syncwarp();
#pragma unroll 4
        for (int j = 0; j < cnt; j++) {
            float4 v = H4[(size_t)ss[wrp][j] * 32 + lane];
            float wj = sw[wrp][j];
            acc.x += wj * v.x;
            acc.y += wj * v.y;
            acc.z += wj * v.z;
            acc.w += wj * v.w;
        }
        __syncwarp();
        p += cnt;
    }

    float4 bb = *(const float4*)&b[lane * 4];
    acc.x = fmaxf(acc.x + bb.x, 0.f);
    acc.y = fmaxf(acc.y + bb.y, 0.f);
    acc.z = fmaxf(acc.z + bb.z, 0.f);
    acc.w = fmaxf(acc.w + bb.w, 0.f);
    ((float4*)Y)[(size_t)i * 32 + lane] = acc;
}

// ---------------- aggregation (40-d) + log_softmax + reg -------------------------
__global__ __launch_bounds__(256) void k_agg40(const float* __restrict__ H3,
                                               const float* __restrict__ b,
                                               float* __restrict__ out, int n,
                                               int reg_idx) {
    if (blockIdx.x == 0 && threadIdx.x == 0) out[reg_idx] = (float)g_reg;

    __shared__ int   ss[8][32];
    __shared__ float sw[8][32];
    const int lane = threadIdx.x & 31;
    const int wrp  = threadIdx.x >> 5;
    const int i = blockIdx.x * 8 + wrp;
    if (i >= n) return;

    float d2 = g_dis[i]; d2 *= d2;
    float a0 = d2 * H3[(size_t)i * DOUT + lane];
    float a1 = (lane < 8) ? d2 * H3[(size_t)i * DOUT + 32 + lane] : 0.f;

    int p = g_rowptr[i];
    const int pe = g_rowptr[i + 1];
    while (p < pe) {
        int cnt = pe - p;
        if (cnt > 32) cnt = 32;
        if (lane < cnt) {
            ss[wrp][lane] = g_csrc[p + lane];
            sw[wrp][lane] = g_cnorm[p + lane];
        }
        __syncwarp();
#pragma unroll 4
        for (int j = 0; j < cnt; j++) {
            int s = ss[wrp][j];
            float wj = sw[wrp][j];
            a0 += wj * H3[(size_t)s * DOUT + lane];
            if (lane < 8) a1 += wj * H3[(size_t)s * DOUT + 32 + lane];
        }
        __syncwarp();
        p += cnt;
    }

    float v0 = a0 + b[lane];
    float v1 = (lane < 8) ? (a1 + b[32 + lane]) : -INFINITY;

    float m = fmaxf(v0, v1);
#pragma unroll
    for (int o = 16; o; o >>= 1) m = fmaxf(m, __shfl_xor_sync(0xffffffffu, m, o));
    float se = expf(v0 - m) + ((lane < 8) ? expf(v1 - m) : 0.f);
#pragma unroll
    for (int o = 16; o; o >>= 1) se += __shfl_xor_sync(0xffffffffu, se, o);
    float ls = m + logf(se);

    out[(size_t)i * DOUT + lane] = v0 - ls;
    if (lane < 8) out[(size_t)i * DOUT + 32 + lane] = v1 - ls;
}

// ---------------- launch ----------------------------------------------------------
extern "C" void kernel_launch(void* const* d_in, const int* in_sizes, int n_in,
                              void* d_out, int out_size) {
    const float* x  = (const float*)d_in[0];
    const int*   ei = (const int*)d_in[1];
    const float* W1 = (const float*)d_in[2];
    const float* b1 = (const float*)d_in[3];
    const float* W2 = (const float*)d_in[4];
    const float* b2 = (const float*)d_in[5];
    const float* W3 = (const float*)d_in[6];
    const float* b3 = (const float*)d_in[7];
    float* out = (float*)d_out;

    const int n = in_sizes[0] / D;      // 40000
    const int E = in_sizes[1] / 2;      // 640000
    const int* src = ei;
    const int* dst = ei + E;

    const int GEMM_SMEM = (D * D + GR * D) * sizeof(float);  // 96 KB
    cudaFuncSetAttribute(k_gemm128, cudaFuncAttributeMaxDynamicSharedMemorySize, GEMM_SMEM);

    const int TB = 256;
    const int eblocks = (E + TB - 1) / TB;
    const int ablocks = (n + 7) / 8;
    const int gblocks = (n + GR - 1) / GR;

    k_stamp<<<1, 1>>>(0);
    k_gemm128<<<gblocks, TB, GEMM_SMEM>>>(x, W1, g_h, n);
    k_stamp<<<1, 1>>>(1);
    k_clear<<<(NN + TB - 1) / TB, TB>>>();
    k_stamp<<<1, 1>>>(2);
    k_deg<<<eblocks, TB>>>(dst, E);
    k_stamp<<<1, 1>>>(3);
    k_scan_part<<<SCB, 256>>>(n);
    k_scan_top<<<1, 256>>>();
    k_scan_down<<<SCB, 256>>>(n, E);
    k_stamp<<<1, 1>>>(4);
    k_scatter<<<eblocks, TB>>>(src, dst, E);
    k_stamp<<<1, 1>>>(5);
    k_reg<<<eblocks, TB>>>(src, dst, E);
    k_stamp<<<1, 1>>>(6);
    k_agg128<<<ablocks, TB>>>(g_h, b1, g_y, n);
    k_stamp<<<1, 1>>>(7);
    k_gemm128<<<gblocks, TB, GEMM_SMEM>>>(g_y, W2, g_h, n);
    k_stamp<<<1, 1>>>(8);
    k_agg128<<<ablocks, TB>>>(g_h, b2, g_y, n);
    k_stamp<<<1, 1>>>(9);
    k_gemm40<<<gblocks, TB>>>(g_y, W3, g_h3, n);
    k_stamp<<<1, 1>>>(10);
    k_agg40<<<ablocks, TB>>>(g_h3, b3, out, n, out_size - 1);
    k_stamp<<<1, 1>>>(11);
    k_print<<<1, 1>>>();
}